// round 12
// baseline (speedup 1.0000x reference)
#include <cuda_runtime.h>
#include <cstdint>

#define IN_F  4096
#define OUT_F 16384
#define NB    8      // batch vectors
#define NP    (NB/2) // batch pairs
#define RPW   8      // rows per warp
#define WARPS 8
#define THREADS (WARPS * 32)          // 256
#define ROWS_PER_CTA (RPW * WARPS)    // 64
#define NCHUNK (IN_F / 128)           // 32 chunks (4 cols/lane each)
#define AROW   (IN_F / 64)            // absmax row stride (64)

__constant__ float NF4_CODE[16] = {
    -1.0f, -0.6961928009986877f, -0.5250730514526367f, -0.39491748809814453f,
    -0.28444138169288635f, -0.18477343022823334f, -0.09105003625154495f, 0.0f,
    0.07958029955625534f, 0.16093020141124725f, 0.24611230194568634f,
    0.33791524171829224f, 0.44070982933044434f, 0.5626170039176941f,
    0.7229568362236023f, 1.0f};

typedef unsigned long long ull;

__device__ __forceinline__ ull pk2(float lo, float hi) {
    ull r;
    asm("mov.b64 %0, {%1, %2};" : "=l"(r)
        : "r"(__float_as_uint(lo)), "r"(__float_as_uint(hi)));
    return r;
}
__device__ __forceinline__ void upk2(ull v, float& lo, float& hi) {
    unsigned int a, b;
    asm("mov.b64 {%0, %1}, %2;" : "=r"(a), "=r"(b) : "l"(v));
    lo = __uint_as_float(a); hi = __uint_as_float(b);
}
__device__ __forceinline__ void fma2(ull& acc, ull a, ull b) {
    asm("fma.rn.f32x2 %0, %1, %2, %0;" : "+l"(acc) : "l"(a), "l"(b));
}
__device__ __forceinline__ ull mul2(ull a, ull b) {
    ull r;
    asm("mul.rn.f32x2 %0, %1, %2;" : "=l"(r) : "l"(a), "l"(b));
    return r;
}

__global__ __launch_bounds__(THREADS, 1)
void nf4_qlinear_kernel(const float* __restrict__ x,
                        const int*   __restrict__ codes,
                        const float* __restrict__ absmax,
                        float*       __restrict__ out) {
    // Pair table: tab2[(c0<<4)|c1] = (nf4[c0], nf4[c1]) packed f32x2.
    // One LDS.64 retrieves two adjacent-column weights.
    __shared__ ull tab2[256];
    const int tid  = threadIdx.x;
    const int lane = tid & 31;
    const int warp = tid >> 5;
    for (int i = tid; i < 256; i += THREADS)
        tab2[i] = pk2(NF4_CODE[i >> 4], NF4_CODE[i & 15]);
    __syncthreads();

    const int row0   = blockIdx.x * ROWS_PER_CTA + warp * RPW;
    const int sel_hi = (lane >= 16);

    // pointer-bump bases (all loads reg + const-immediate offsets)
    const int4*  cp = reinterpret_cast<const int4*>(
                          codes + (size_t)row0 * IN_F) + lane;
    const float* ap = absmax + (size_t)row0 * AROW + sel_hi;
    const float* xp = x + lane * 4;

    ull acc[RPW][NP];    // acc[r][p] packs (batch 2p, batch 2p+1)
    #pragma unroll
    for (int r = 0; r < RPW; ++r)
        #pragma unroll
        for (int p = 0; p < NP; ++p) acc[r][p] = 0ULL;

    // ---- consume one chunk from prefetched codes + absmax ----
    auto consume = [&](const int4* cv, const float* am, int xo) {
        // cross-batch x pairs for this chunk's 4 cols (reused by 8 rows)
        ull xq[NP][4];
        #pragma unroll
        for (int p = 0; p < NP; ++p) {
            const float4 xe = *reinterpret_cast<const float4*>(
                xp + xo + (2 * p) * IN_F);
            const float4 xo4 = *reinterpret_cast<const float4*>(
                xp + xo + (2 * p + 1) * IN_F);
            xq[p][0] = pk2(xe.x, xo4.x);
            xq[p][1] = pk2(xe.y, xo4.y);
            xq[p][2] = pk2(xe.z, xo4.z);
            xq[p][3] = pk2(xe.w, xo4.w);
        }
        #pragma unroll
        for (int r = 0; r < RPW; ++r) {
            const ull a2  = pk2(am[r], am[r]);
            const ull t01 = mul2(tab2[(cv[r].x << 4) | cv[r].y], a2);
            const ull t23 = mul2(tab2[(cv[r].z << 4) | cv[r].w], a2);
            float w0, w1, w2, w3;
            upk2(t01, w0, w1);
            upk2(t23, w2, w3);
            const ull s0 = pk2(w0, w0), s1 = pk2(w1, w1);
            const ull s2 = pk2(w2, w2), s3 = pk2(w3, w3);
            #pragma unroll
            for (int p = 0; p < NP; ++p) {
                fma2(acc[r][p], s0, xq[p][0]);
                fma2(acc[r][p], s1, xq[p][1]);
                fma2(acc[r][p], s2, xq[p][2]);
                fma2(acc[r][p], s3, xq[p][3]);
            }
        }
    };

    // ---- distance-1 double-buffered prefetch, unrolled x2 ----
    int4  cvA[RPW], cvB[RPW];
    float amA[RPW], amB[RPW];
    #pragma unroll
    for (int r = 0; r < RPW; ++r) {
        cvA[r] = __ldcs(cp + r * (IN_F / 4));
        amA[r] = __ldg(ap + r * AROW);
    }

    #pragma unroll 1
    for (int j = 0; j < NCHUNK; j += 2) {
        #pragma unroll
        for (int r = 0; r < RPW; ++r) {                 // prefetch chunk j+1
            cvB[r] = __ldcs(cp + 32 + r * (IN_F / 4));
            amB[r] = __ldg(ap + 2 + r * AROW);
        }
        consume(cvA, amA, 0);

        if (j + 2 < NCHUNK) {
            #pragma unroll
            for (int r = 0; r < RPW; ++r) {             // prefetch chunk j+2
                cvA[r] = __ldcs(cp + 64 + r * (IN_F / 4));
                amA[r] = __ldg(ap + 4 + r * AROW);
            }
        }
        consume(cvB, amB, 128);

        cp += 64;
        ap += 4;
        xp += 256;
    }

    // warp-reduce packed (even,odd) batch sums, store
    #pragma unroll
    for (int r = 0; r < RPW; ++r) {
        #pragma unroll
        for (int p = 0; p < NP; ++p) {
            float se, so;
            upk2(acc[r][p], se, so);
            #pragma unroll
            for (int off = 16; off > 0; off >>= 1) {
                se += __shfl_xor_sync(0xffffffffu, se, off);
                so += __shfl_xor_sync(0xffffffffu, so, off);
            }
            if (lane == 0) {
                out[(size_t)(2 * p)     * OUT_F + row0 + r] = se;
                out[(size_t)(2 * p + 1) * OUT_F + row0 + r] = so;
            }
        }
    }
}

extern "C" void kernel_launch(void* const* d_in, const int* in_sizes, int n_in,
                              void* d_out, int out_size) {
    const float* x      = (const float*)d_in[0];   // [8,1,4096] f32
    const int*   codes  = (const int*)d_in[1];     // [16384,4096] i32 (0..15)
    const float* absmax = (const float*)d_in[2];   // [16384,64] f32
    float*       out    = (float*)d_out;           // [8,1,16384] f32

    (void)in_sizes; (void)n_in; (void)out_size;
    nf4_qlinear_kernel<<<OUT_F / ROWS_PER_CTA, THREADS>>>(x, codes, absmax, out);
}

// round 13
// speedup vs baseline: 1.0606x; 1.0606x over previous
#include <cuda_runtime.h>
#include <cstdint>

#define IN_F  4096
#define OUT_F 16384
#define NB    8      // batch vectors
#define NP    (NB/2) // batch pairs
#define RPW   8      // rows per warp
#define WARPS 4
#define THREADS (WARPS * 32)          // 128
#define ROWS_PER_CTA (RPW * WARPS)    // 32
#define NCHUNK (IN_F / 128)           // 32 chunks (4 cols/lane each)
#define AROW   (IN_F / 64)            // absmax row stride (64)

__constant__ float NF4_CODE[16] = {
    -1.0f, -0.6961928009986877f, -0.5250730514526367f, -0.39491748809814453f,
    -0.28444138169288635f, -0.18477343022823334f, -0.09105003625154495f, 0.0f,
    0.07958029955625534f, 0.16093020141124725f, 0.24611230194568634f,
    0.33791524171829224f, 0.44070982933044434f, 0.5626170039176941f,
    0.7229568362236023f, 1.0f};

typedef unsigned long long ull;

// cross-batch packed x: g_xT[p*IN_F + col] = (x[2p][col], x[2p+1][col])
__device__ ull g_xT[NP * IN_F];

__device__ __forceinline__ ull pk2(float lo, float hi) {
    ull r;
    asm("mov.b64 %0, {%1, %2};" : "=l"(r)
        : "r"(__float_as_uint(lo)), "r"(__float_as_uint(hi)));
    return r;
}
__device__ __forceinline__ void upk2(ull v, float& lo, float& hi) {
    unsigned int a, b;
    asm("mov.b64 {%0, %1}, %2;" : "=r"(a), "=r"(b) : "l"(v));
    lo = __uint_as_float(a); hi = __uint_as_float(b);
}
__device__ __forceinline__ void fma2(ull& acc, ull a, ull b) {
    asm("fma.rn.f32x2 %0, %1, %2, %0;" : "+l"(acc) : "l"(a), "l"(b));
}
__device__ __forceinline__ ull mul2(ull a, ull b) {
    ull r;
    asm("mul.rn.f32x2 %0, %1, %2;" : "=l"(r) : "l"(a), "l"(b));
    return r;
}

// ---- prepass: build cross-batch packed x (once per launch, ~2.6us) ----
__global__ void xt_kernel(const float* __restrict__ x) {
    const int idx = blockIdx.x * 256 + threadIdx.x;   // 0 .. NP*IN_F-1
    const int p   = idx >> 12;
    const int col = idx & (IN_F - 1);
    g_xT[idx] = pk2(x[(2 * p) * IN_F + col], x[(2 * p + 1) * IN_F + col]);
}

__global__ __launch_bounds__(THREADS, 2)
void nf4_qlinear_kernel(const int*   __restrict__ codes,
                        const float* __restrict__ absmax,
                        float*       __restrict__ out) {
    // splat NF4 table: tabS[c] = (nf4[c], nf4[c]); disjoint bank pairs +
    // broadcast -> LDS.64 conflict-free for any code pattern
    __shared__ ull tabS[16];
    const int tid  = threadIdx.x;
    const int lane = tid & 31;
    const int warp = tid >> 5;
    if (tid < 16) tabS[tid] = pk2(NF4_CODE[tid], NF4_CODE[tid]);
    __syncthreads();

    const int row0   = blockIdx.x * ROWS_PER_CTA + warp * RPW;
    const int sel_hi = (lane >= 16);

    // pointer-bump bases (all loads reg + const-immediate offsets)
    const int4*  cp = reinterpret_cast<const int4*>(
                          codes + (size_t)row0 * IN_F) + lane;
    const float* ap = absmax + (size_t)row0 * AROW + sel_hi;
    const ull*   xp = g_xT + lane * 4;

    ull acc[RPW][NP];    // acc[r][p] packs (batch 2p, batch 2p+1)
    #pragma unroll
    for (int r = 0; r < RPW; ++r)
        #pragma unroll
        for (int p = 0; p < NP; ++p) acc[r][p] = 0ULL;

    // ---- consume one chunk from prefetched codes + absmax ----
    auto consume = [&](const int4* cv, const float* am, int xo) {
        // pre-packed cross-batch x pairs for this chunk's 4 cols
        ull xq0[NP], xq1[NP], xq2[NP], xq3[NP];
        #pragma unroll
        for (int p = 0; p < NP; ++p) {
            const ulonglong2 xv0 = *reinterpret_cast<const ulonglong2*>(
                xp + xo + (size_t)p * IN_F);
            const ulonglong2 xv1 = *reinterpret_cast<const ulonglong2*>(
                xp + xo + (size_t)p * IN_F + 2);
            xq0[p] = xv0.x; xq1[p] = xv0.y;
            xq2[p] = xv1.x; xq3[p] = xv1.y;
        }
        #pragma unroll
        for (int r = 0; r < RPW; ++r) {
            const ull a2 = pk2(am[r], am[r]);
            const ull s0 = mul2(tabS[cv[r].x], a2);
            const ull s1 = mul2(tabS[cv[r].y], a2);
            const ull s2 = mul2(tabS[cv[r].z], a2);
            const ull s3 = mul2(tabS[cv[r].w], a2);
            #pragma unroll
            for (int p = 0; p < NP; ++p) {
                fma2(acc[r][p], s0, xq0[p]);
                fma2(acc[r][p], s1, xq1[p]);
                fma2(acc[r][p], s2, xq2[p]);
                fma2(acc[r][p], s3, xq3[p]);
            }
        }
    };

    // ---- distance-1 double-buffered prefetch, unrolled x2 ----
    int4  cvA[RPW], cvB[RPW];
    float amA[RPW], amB[RPW];
    #pragma unroll
    for (int r = 0; r < RPW; ++r) {
        cvA[r] = __ldcs(cp + r * (IN_F / 4));
        amA[r] = __ldg(ap + r * AROW);
    }

    #pragma unroll 1
    for (int j = 0; j < NCHUNK; j += 2) {
        #pragma unroll
        for (int r = 0; r < RPW; ++r) {                 // prefetch chunk j+1
            cvB[r] = __ldcs(cp + 32 + r * (IN_F / 4));
            amB[r] = __ldg(ap + 2 + r * AROW);
        }
        consume(cvA, amA, 0);

        if (j + 2 < NCHUNK) {
            #pragma unroll
            for (int r = 0; r < RPW; ++r) {             // prefetch chunk j+2
                cvA[r] = __ldcs(cp + 64 + r * (IN_F / 4));
                amA[r] = __ldg(ap + 4 + r * AROW);
            }
        }
        consume(cvB, amB, 128);

        cp += 64;
        ap += 4;
        xp += 256;
    }

    // warp-reduce packed (even,odd) batch sums, store
    #pragma unroll
    for (int r = 0; r < RPW; ++r) {
        #pragma unroll
        for (int p = 0; p < NP; ++p) {
            float se, so;
            upk2(acc[r][p], se, so);
            #pragma unroll
            for (int off = 16; off > 0; off >>= 1) {
                se += __shfl_xor_sync(0xffffffffu, se, off);
                so += __shfl_xor_sync(0xffffffffu, so, off);
            }
            if (lane == 0) {
                out[(size_t)(2 * p)     * OUT_F + row0 + r] = se;
                out[(size_t)(2 * p + 1) * OUT_F + row0 + r] = so;
            }
        }
    }
}

extern "C" void kernel_launch(void* const* d_in, const int* in_sizes, int n_in,
                              void* d_out, int out_size) {
    const float* x      = (const float*)d_in[0];   // [8,1,4096] f32
    const int*   codes  = (const int*)d_in[1];     // [16384,4096] i32 (0..15)
    const float* absmax = (const float*)d_in[2];   // [16384,64] f32
    float*       out    = (float*)d_out;           // [8,1,16384] f32

    (void)in_sizes; (void)n_in; (void)out_size;
    xt_kernel<<<(NP * IN_F) / 256, 256>>>(x);
    nf4_qlinear_kernel<<<OUT_F / ROWS_PER_CTA, THREADS>>>(codes, absmax, out);
}

// round 14
// speedup vs baseline: 1.2664x; 1.1941x over previous
#include <cuda_runtime.h>
#include <cstdint>

#define IN_F  4096
#define OUT_F 16384
#define NB    8      // batch vectors
#define NP    (NB/2) // batch pairs
#define RPW   8      // rows per warp
#define WARPS 4
#define THREADS (WARPS * 32)          // 128
#define ROWS_PER_CTA (RPW * WARPS)    // 32
#define NCHUNK (IN_F / 128)           // 32 chunks (4 cols/lane each)
#define AROW   (IN_F / 64)            // absmax row stride (64)

__constant__ float NF4_CODE[16] = {
    -1.0f, -0.6961928009986877f, -0.5250730514526367f, -0.39491748809814453f,
    -0.28444138169288635f, -0.18477343022823334f, -0.09105003625154495f, 0.0f,
    0.07958029955625534f, 0.16093020141124725f, 0.24611230194568634f,
    0.33791524171829224f, 0.44070982933044434f, 0.5626170039176941f,
    0.7229568362236023f, 1.0f};

typedef unsigned long long ull;

// cross-batch packed x: g_xT[p*IN_F + col] = (x[2p][col], x[2p+1][col])
__device__ ull g_xT[NP * IN_F];

__device__ __forceinline__ ull pk2(float lo, float hi) {
    ull r;
    asm("mov.b64 %0, {%1, %2};" : "=l"(r)
        : "r"(__float_as_uint(lo)), "r"(__float_as_uint(hi)));
    return r;
}
__device__ __forceinline__ void upk2(ull v, float& lo, float& hi) {
    unsigned int a, b;
    asm("mov.b64 {%0, %1}, %2;" : "=r"(a), "=r"(b) : "l"(v));
    lo = __uint_as_float(a); hi = __uint_as_float(b);
}
__device__ __forceinline__ void fma2(ull& acc, ull a, ull b) {
    asm("fma.rn.f32x2 %0, %1, %2, %0;" : "+l"(acc) : "l"(a), "l"(b));
}
__device__ __forceinline__ ull mul2(ull a, ull b) {
    ull r;
    asm("mul.rn.f32x2 %0, %1, %2;" : "=l"(r) : "l"(a), "l"(b));
    return r;
}

// ---- prepass: build cross-batch packed x (once per launch, ~1.5us) ----
__global__ void xt_kernel(const float* __restrict__ x) {
    const int idx = blockIdx.x * 256 + threadIdx.x;   // 0 .. NP*IN_F-1
    const int p   = idx >> 12;
    const int col = idx & (IN_F - 1);
    g_xT[idx] = pk2(x[(2 * p) * IN_F + col], x[(2 * p + 1) * IN_F + col]);
}

__global__ __launch_bounds__(THREADS, 2)
void nf4_qlinear_kernel(const int*   __restrict__ codes,
                        const float* __restrict__ absmax,
                        float*       __restrict__ out) {
    // splat NF4 table: tabS[c] = (nf4[c], nf4[c]); disjoint bank pairs +
    // broadcast -> LDS.64 conflict-free for any code pattern
    __shared__ ull tabS[16];
    const int tid  = threadIdx.x;
    const int lane = tid & 31;
    const int warp = tid >> 5;
    if (tid < 16) tabS[tid] = pk2(NF4_CODE[tid], NF4_CODE[tid]);
    __syncthreads();

    const int row0   = blockIdx.x * ROWS_PER_CTA + warp * RPW;
    const int sel_hi = (lane >= 16);

    // pointer-bump bases (all loads reg + const-immediate offsets)
    const int4*  cp = reinterpret_cast<const int4*>(
                          codes + (size_t)row0 * IN_F) + lane;
    const float* ap = absmax + (size_t)row0 * AROW + sel_hi;
    const ull*   xp = g_xT + lane * 4;

    ull acc[RPW][NP];    // acc[r][p] packs (batch 2p, batch 2p+1)
    #pragma unroll
    for (int r = 0; r < RPW; ++r)
        #pragma unroll
        for (int p = 0; p < NP; ++p) acc[r][p] = 0ULL;

    // ---- consume one chunk from prefetched codes + absmax ----
    auto consume = [&](const int4* cv, const float* am, int xo) {
        ull xq0[NP], xq1[NP], xq2[NP], xq3[NP];
        #pragma unroll
        for (int p = 0; p < NP; ++p) {
            const ulonglong2 xv0 = *reinterpret_cast<const ulonglong2*>(
                xp + xo + (size_t)p * IN_F);
            const ulonglong2 xv1 = *reinterpret_cast<const ulonglong2*>(
                xp + xo + (size_t)p * IN_F + 2);
            xq0[p] = xv0.x; xq1[p] = xv0.y;
            xq2[p] = xv1.x; xq3[p] = xv1.y;
        }
        #pragma unroll
        for (int r = 0; r < RPW; ++r) {
            const ull a2 = pk2(am[r], am[r]);
            const ull s0 = mul2(tabS[cv[r].x], a2);
            const ull s1 = mul2(tabS[cv[r].y], a2);
            const ull s2 = mul2(tabS[cv[r].z], a2);
            const ull s3 = mul2(tabS[cv[r].w], a2);
            #pragma unroll
            for (int p = 0; p < NP; ++p) {
                fma2(acc[r][p], s0, xq0[p]);
                fma2(acc[r][p], s1, xq1[p]);
                fma2(acc[r][p], s2, xq2[p]);
                fma2(acc[r][p], s3, xq3[p]);
            }
        }
    };

    // ---- distance-2 triple-buffered prefetch, unrolled x3 ----
    int4  cvA[RPW], cvB[RPW], cvC[RPW];
    float amA[RPW], amB[RPW], amC[RPW];
    #pragma unroll
    for (int r = 0; r < RPW; ++r) {          // chunks 0 and 1
        cvA[r] = __ldcs(cp + r * (IN_F / 4));
        amA[r] = __ldg(ap + r * AROW);
        cvB[r] = __ldcs(cp + 32 + r * (IN_F / 4));
        amB[r] = __ldg(ap + 2 + r * AROW);
    }

    #pragma unroll 1
    for (int it = 0; it < 10; ++it) {        // chunks 3*it .. 3*it+2
        #pragma unroll
        for (int r = 0; r < RPW; ++r) {      // prefetch chunk j+2
            cvC[r] = __ldcs(cp + 64 + r * (IN_F / 4));
            amC[r] = __ldg(ap + 4 + r * AROW);
        }
        consume(cvA, amA, 0);
        #pragma unroll
        for (int r = 0; r < RPW; ++r) {      // prefetch chunk j+3
            cvA[r] = __ldcs(cp + 96 + r * (IN_F / 4));
            amA[r] = __ldg(ap + 6 + r * AROW);
        }
        consume(cvB, amB, 128);
        #pragma unroll
        for (int r = 0; r < RPW; ++r) {      // prefetch chunk j+4
            cvB[r] = __ldcs(cp + 128 + r * (IN_F / 4));
            amB[r] = __ldg(ap + 8 + r * AROW);
        }
        consume(cvC, amC, 256);
        cp += 96;     // 3 chunks
        ap += 6;
        xp += 384;
    }
    // epilogue: chunks 30 (in A) and 31 (in B)
    consume(cvA, amA, 0);
    consume(cvB, amB, 128);

    // warp-reduce packed (even,odd) batch sums, store
    #pragma unroll
    for (int r = 0; r < RPW; ++r) {
        #pragma unroll
        for (int p = 0; p < NP; ++p) {
            float se, so;
            upk2(acc[r][p], se, so);
            #pragma unroll
            for (int off = 16; off > 0; off >>= 1) {
                se += __shfl_xor_sync(0xffffffffu, se, off);
                so += __shfl_xor_sync(0xffffffffu, so, off);
            }
            if (lane == 0) {
                out[(size_t)(2 * p)     * OUT_F + row0 + r] = se;
                out[(size_t)(2 * p + 1) * OUT_F + row0 + r] = so;
            }
        }
    }
}

extern "C" void kernel_launch(void* const* d_in, const int* in_sizes, int n_in,
                              void* d_out, int out_size) {
    const float* x      = (const float*)d_in[0];   // [8,1,4096] f32
    const int*   codes  = (const int*)d_in[1];     // [16384,4096] i32 (0..15)
    const float* absmax = (const float*)d_in[2];   // [16384,64] f32
    float*       out    = (float*)d_out;           // [8,1,16384] f32

    (void)in_sizes; (void)n_in; (void)out_size;
    xt_kernel<<<(NP * IN_F) / 256, 256>>>(x);
    nf4_qlinear_kernel<<<OUT_F / ROWS_PER_CTA, THREADS>>>(codes, absmax, out);
}